// round 1
// baseline (speedup 1.0000x reference)
#include <cuda_runtime.h>
#include <math.h>

#define BB 8
#define CC 4
#define HH 512
#define WW 512
#define TILE_H 8
#define SMW (WW + 2)
#define NSTRIP (HH / TILE_H)      // 64
#define NPLANE (BB * CC)          // 32
#define NBLK (NSTRIP * NPLANE)    // 2048
#define NTHREADS 256

// Per-block partials: [pt, p, t, mismatch] — every block writes its own slot,
// so no zeroing and no atomics (fully deterministic).
__device__ float g_part[NBLK * 4];

__global__ __launch_bounds__(NTHREADS) void loss_main(
    const float* __restrict__ logits, const float* __restrict__ targets)
{
    __shared__ float sP[(TILE_H + 2) * SMW];  // sigmoid(logits), zero-padded halo
    __shared__ float sT[(TILE_H + 2) * SMW];  // targets, zero-padded halo
    __shared__ float red[NTHREADS / 32][4];

    const int plane = blockIdx.y;             // b*C + c
    const int row0  = blockIdx.x * TILE_H;
    const float* lg = logits  + (size_t)plane * HH * WW;
    const float* tg = targets + (size_t)plane * HH * WW;
    const int tid = threadIdx.x;

    // Load TILE_H+2 rows x (WW+2) cols with zero padding outside the image.
    for (int i = tid; i < (TILE_H + 2) * SMW; i += NTHREADS) {
        int r = i / SMW;
        int c = i - r * SMW;
        int gr = row0 - 1 + r;
        int gc = c - 1;
        bool in = (gr >= 0) && (gr < HH) && (gc >= 0) && (gc < WW);
        float pv = 0.0f, tv = 0.0f;
        if (in) {
            int gi = gr * WW + gc;
            float lv = lg[gi];
            pv = 1.0f / (1.0f + expf(-lv));
            tv = tg[gi];
        }
        sP[i] = pv;
        sT[i] = tv;
    }
    __syncthreads();

    float s_pt = 0.0f, s_p = 0.0f, s_t = 0.0f, s_m = 0.0f;
    #pragma unroll
    for (int k = 0; k < (TILE_H * WW) / NTHREADS; k++) {
        int i = tid + k * NTHREADS;          // 0 .. TILE_H*WW-1
        int r = i >> 9;                      // / 512
        int c = i & (WW - 1);
        int base = (r + 1) * SMW + (c + 1);  // center in smem

        float p = sP[base];
        float t = sT[base];
        s_pt += p * t;
        s_p  += p;
        s_t  += t;

        // Sobel on probs (cross-correlation, matches lax.conv)
        float a00 = sP[base - SMW - 1], a01 = sP[base - SMW], a02 = sP[base - SMW + 1];
        float a10 = sP[base - 1],                              a12 = sP[base + 1];
        float a20 = sP[base + SMW - 1], a21 = sP[base + SMW], a22 = sP[base + SMW + 1];
        float gx = (a02 - a00) + 2.0f * (a12 - a10) + (a22 - a20);
        float gy = (a20 - a00) + 2.0f * (a21 - a01) + (a22 - a02);
        bool pb = (gx * gx + gy * gy) > 0.25f;   // == (sqrt > 0.5)

        // Sobel on targets
        float b00 = sT[base - SMW - 1], b01 = sT[base - SMW], b02 = sT[base - SMW + 1];
        float b10 = sT[base - 1],                              b12 = sT[base + 1];
        float b20 = sT[base + SMW - 1], b21 = sT[base + SMW], b22 = sT[base + SMW + 1];
        float hx = (b02 - b00) + 2.0f * (b12 - b10) + (b22 - b20);
        float hy = (b20 - b00) + 2.0f * (b21 - b01) + (b22 - b02);
        bool tb = (hx * hx + hy * hy) > 0.25f;

        s_m += (pb != tb) ? 1.0f : 0.0f;         // BCE of binary maps = 100*mismatch_frac
    }

    // warp reduce
    #pragma unroll
    for (int o = 16; o > 0; o >>= 1) {
        s_pt += __shfl_down_sync(0xffffffffu, s_pt, o);
        s_p  += __shfl_down_sync(0xffffffffu, s_p,  o);
        s_t  += __shfl_down_sync(0xffffffffu, s_t,  o);
        s_m  += __shfl_down_sync(0xffffffffu, s_m,  o);
    }
    int w = tid >> 5, lane = tid & 31;
    if (lane == 0) {
        red[w][0] = s_pt; red[w][1] = s_p; red[w][2] = s_t; red[w][3] = s_m;
    }
    __syncthreads();
    if (tid == 0) {
        float a = 0.f, b = 0.f, c2 = 0.f, d = 0.f;
        #pragma unroll
        for (int j = 0; j < NTHREADS / 32; j++) {
            a += red[j][0]; b += red[j][1]; c2 += red[j][2]; d += red[j][3];
        }
        int bid = plane * NSTRIP + blockIdx.x;
        g_part[bid * 4 + 0] = a;
        g_part[bid * 4 + 1] = b;
        g_part[bid * 4 + 2] = c2;
        g_part[bid * 4 + 3] = d;
    }
}

__global__ void finalize(const float* __restrict__ cw, float* __restrict__ out)
{
    __shared__ float dice_pl[NPLANE];
    __shared__ float msum[NTHREADS];
    int tid = threadIdx.x;

    // mismatch total (strided over all 2048 partials)
    float m = 0.0f;
    for (int j = tid; j < NBLK; j += NTHREADS) m += g_part[j * 4 + 3];
    msum[tid] = m;

    // per-plane dice (threads 0..31, one plane each, 64 strips)
    if (tid < NPLANE) {
        float a = 0.f, b = 0.f, c = 0.f;
        for (int j = 0; j < NSTRIP; j++) {
            int bid = tid * NSTRIP + j;
            a += g_part[bid * 4 + 0];
            b += g_part[bid * 4 + 1];
            c += g_part[bid * 4 + 2];
        }
        dice_pl[tid] = (2.0f * a + 1.0f) / (b + c + 1.0f);  // SMOOTH=1
    }
    __syncthreads();

    if (tid == 0) {
        float mt = 0.0f;
        for (int j = 0; j < NTHREADS; j++) mt += msum[j];

        float wsum = 0.0f, dl = 0.0f;
        for (int c = 0; c < CC; c++) {
            float acc = 0.0f;
            for (int b = 0; b < BB; b++) acc += dice_pl[b * CC + c];
            float class_dice = 1.0f - acc / (float)BB;
            dl += cw[c] * class_dice;
            wsum += cw[c];
        }
        dl /= wsum;

        float bl = 100.0f * mt / (float)((size_t)BB * CC * HH * WW);
        *out = 0.7f * dl + 0.3f * bl;
    }
}

extern "C" void kernel_launch(void* const* d_in, const int* in_sizes, int n_in,
                              void* d_out, int out_size)
{
    const float* logits  = (const float*)d_in[0];
    const float* targets = (const float*)d_in[1];
    const float* cw      = (const float*)d_in[2];

    dim3 grid(NSTRIP, NPLANE);
    loss_main<<<grid, NTHREADS>>>(logits, targets);
    finalize<<<1, NTHREADS>>>(cw, (float*)d_out);
}

// round 2
// speedup vs baseline: 1.3109x; 1.3109x over previous
#include <cuda_runtime.h>
#include <math.h>

#define BB 8
#define CC 4
#define HH 512
#define WW 512
#define TILE_H 16
#define SMW (WW + 2)
#define NSTRIP (HH / TILE_H)      // 32
#define NPLANE (BB * CC)          // 32
#define NBLK (NSTRIP * NPLANE)    // 1024
#define NTHREADS 512
#define NWARP (NTHREADS / 32)

// Per-block partials: (sum p*t, sum p, sum t, mismatch count) — one float4 per
// block, each block writes only its own slot (deterministic, no float atomics).
__device__ float4 g_part[NBLK];
__device__ int g_ctr = 0;

__global__ __launch_bounds__(NTHREADS) void loss_fused(
    const float* __restrict__ logits, const float* __restrict__ targets,
    const float* __restrict__ cw, float* __restrict__ out)
{
    __shared__ float sP[(TILE_H + 2) * SMW];         // sigmoid(logits), zero halo
    __shared__ unsigned char sT[(TILE_H + 2) * SMW]; // binary targets, zero halo
    __shared__ float red[NWARP][4];
    __shared__ float s_dice[NPLANE];
    __shared__ float s_mm[NPLANE];
    __shared__ int s_isLast;

    const int plane = blockIdx.y;             // b*C + c
    const int row0  = blockIdx.x * TILE_H;
    const float* lg = logits  + (size_t)plane * HH * WW;
    const float* tg = targets + (size_t)plane * HH * WW;
    const int tid = threadIdx.x;

    // ---- Stage TILE_H+2 rows x (WW+2) cols, zero-padded outside the image ----
    for (int i = tid; i < (TILE_H + 2) * SMW; i += NTHREADS) {
        int r = i / SMW;
        int c = i - r * SMW;
        int gr = row0 - 1 + r;
        int gc = c - 1;
        float pv = 0.0f, tv = 0.0f;
        if ((gr >= 0) & (gr < HH) & (gc >= 0) & (gc < WW)) {
            int gi = gr * WW + gc;
            float lv = lg[gi];
            // sigmoid: 1 MUFU.EX2 + 1 MUFU.RCP, ~2 ulp
            pv = __fdividef(1.0f, 1.0f + __expf(-lv));
            tv = tg[gi];                       // exactly 0.0 or 1.0
        }
        sP[i] = pv;
        sT[i] = (unsigned char)tv;
    }
    __syncthreads();

    // ---- Rolling-window Sobel: thread owns column c, walks down TILE_H rows --
    const int c = tid;   // padded cols read: c (left), c+1 (mid), c+2 (right)

    // prime rows 0 and 1 (padded)
    float l = sP[c], mf = sP[c + 1], rr = sP[c + 2];
    float sA0 = __fmaf_rn(2.0f, mf, l + rr);
    float dA0 = rr - l;
    int il = sT[c], im = sT[c + 1], ir = sT[c + 2];
    int sB0 = il + 2 * im + ir;
    int dB0 = ir - il;

    l = sP[SMW + c]; mf = sP[SMW + c + 1]; rr = sP[SMW + c + 2];
    float sA1 = __fmaf_rn(2.0f, mf, l + rr);
    float dA1 = rr - l;
    float m1  = mf;                       // center prob of middle row
    il = sT[SMW + c]; im = sT[SMW + c + 1]; ir = sT[SMW + c + 2];
    int sB1 = il + 2 * im + ir;
    int dB1 = ir - il;
    int tmid = im;                        // center target of middle row

    float s_pt = 0.0f, s_p = 0.0f;
    int   s_ti = 0,    s_mi = 0;

    #pragma unroll
    for (int r = 0; r < TILE_H; r++) {
        int off = (r + 2) * SMW + c;
        l = sP[off]; mf = sP[off + 1]; rr = sP[off + 2];
        float sA2 = __fmaf_rn(2.0f, mf, l + rr);
        float dA2 = rr - l;
        float gx = __fmaf_rn(2.0f, dA1, dA0 + dA2);
        float gy = sA2 - sA0;
        bool pb = __fmaf_rn(gx, gx, gy * gy) > 0.25f;   // == (sobel mag > 0.5)

        il = sT[off]; im = sT[off + 1]; ir = sT[off + 2];
        int sB2 = il + 2 * im + ir;
        int dB2 = ir - il;
        int hx = dB0 + 2 * dB1 + dB2;
        int hy = sB2 - sB0;
        bool tb = (hx | hy) != 0;                       // integer Sobel, exact

        float tf = (float)tmid;
        s_pt = __fmaf_rn(m1, tf, s_pt);
        s_p += m1;
        s_ti += tmid;
        s_mi += (pb != tb);                             // BCE(binary) = 100*mismatch

        sA0 = sA1; sA1 = sA2; dA0 = dA1; dA1 = dA2; m1 = mf;
        sB0 = sB1; sB1 = sB2; dB0 = dB1; dB1 = dB2; tmid = im;
    }

    // ---- block reduce 4 accumulators ----
    float s_t = (float)s_ti, s_m = (float)s_mi;
    #pragma unroll
    for (int o = 16; o > 0; o >>= 1) {
        s_pt += __shfl_down_sync(0xffffffffu, s_pt, o);
        s_p  += __shfl_down_sync(0xffffffffu, s_p,  o);
        s_t  += __shfl_down_sync(0xffffffffu, s_t,  o);
        s_m  += __shfl_down_sync(0xffffffffu, s_m,  o);
    }
    int w = tid >> 5, lane = tid & 31;
    if (lane == 0) {
        red[w][0] = s_pt; red[w][1] = s_p; red[w][2] = s_t; red[w][3] = s_m;
    }
    __syncthreads();
    if (tid == 0) {
        float a = 0.f, b = 0.f, c2 = 0.f, d = 0.f;
        #pragma unroll
        for (int j = 0; j < NWARP; j++) {
            a += red[j][0]; b += red[j][1]; c2 += red[j][2]; d += red[j][3];
        }
        g_part[plane * NSTRIP + blockIdx.x] = make_float4(a, b, c2, d);

        // last-block election
        __threadfence();
        int v = atomicAdd(&g_ctr, 1);
        s_isLast = (v == NBLK - 1);
    }
    __syncthreads();

    // ---- final reduction in the last block ----
    if (s_isLast) {
        __threadfence();
        if (tid < NPLANE) {
            float a = 0.f, b = 0.f, c2 = 0.f, m = 0.f;
            for (int s = 0; s < NSTRIP; s++) {
                float4 v = g_part[tid * NSTRIP + s];
                a += v.x; b += v.y; c2 += v.z; m += v.w;
            }
            s_dice[tid] = (2.0f * a + 1.0f) / (b + c2 + 1.0f);  // SMOOTH=1
            s_mm[tid] = m;
        }
        __syncthreads();
        if (tid == 0) {
            float mt = 0.0f;
            #pragma unroll
            for (int j = 0; j < NPLANE; j++) mt += s_mm[j];

            float wsum = 0.0f, dl = 0.0f;
            #pragma unroll
            for (int cc = 0; cc < CC; cc++) {
                float acc = 0.0f;
                #pragma unroll
                for (int b = 0; b < BB; b++) acc += s_dice[b * CC + cc];
                dl += cw[cc] * (1.0f - acc / (float)BB);
                wsum += cw[cc];
            }
            dl /= wsum;
            float bl = 100.0f * mt / (float)((long long)BB * CC * HH * WW);
            out[0] = 0.7f * dl + 0.3f * bl;
            g_ctr = 0;   // reset for next graph replay
        }
    }
}

extern "C" void kernel_launch(void* const* d_in, const int* in_sizes, int n_in,
                              void* d_out, int out_size)
{
    const float* logits  = (const float*)d_in[0];
    const float* targets = (const float*)d_in[1];
    const float* cw      = (const float*)d_in[2];

    dim3 grid(NSTRIP, NPLANE);
    loss_fused<<<grid, NTHREADS>>>(logits, targets, cw, (float*)d_out);
}

// round 3
// speedup vs baseline: 2.4619x; 1.8780x over previous
#include <cuda_runtime.h>
#include <math.h>

#define BB 8
#define CC 4
#define HH 512
#define WW 512
#define TILE_H 16
#define SMW4 520                  // padded row width (floats / bytes): 4 + 512 + 4
#define NROWS (TILE_H + 2)        // 18 smem rows
#define NSTRIP (HH / TILE_H)      // 32
#define NPLANE (BB * CC)          // 32
#define NBLK (NSTRIP * NPLANE)    // 1024
#define NT 256
#define NWARP (NT / 32)

// Per-block partials (sum p*t, sum p, sum t, mismatch) — deterministic slots.
__device__ float4 g_part[NBLK];
__device__ int g_ctr = 0;

struct HR { float s0, s1, s2, s3, d0, d1, d2, d3; unsigned sb, db; };

__device__ __forceinline__ HR hrow(const float* __restrict__ pr,
                                   const unsigned char* __restrict__ tr)
{
    HR h;
    float4 v = *(const float4*)pr;
    float pl = pr[-1], prr = pr[4];
    h.s0 = __fmaf_rn(2.f, v.x, pl + v.y);  h.d0 = v.y - pl;
    h.s1 = __fmaf_rn(2.f, v.y, v.x + v.z); h.d1 = v.z - v.x;
    h.s2 = __fmaf_rn(2.f, v.z, v.y + v.w); h.d2 = v.w - v.y;
    h.s3 = __fmaf_rn(2.f, v.w, v.z + prr); h.d3 = prr - v.z;
    unsigned w  = *(const unsigned*)tr;
    unsigned bl = tr[-1], br = tr[4];
    unsigned wl = (w << 8) | bl;            // lane i = t[i-1]
    unsigned wr = (w >> 8) | (br << 24);    // lane i = t[i+1]
    h.sb = wl + 2u * w + wr;                // lanes in [0,4]
    h.db = (wr + 0x02020202u) - wl;         // lanes in [1,3] (bias +2)
    return h;
}

__global__ __launch_bounds__(NT, 4) void loss_fused(
    const float* __restrict__ logits, const float* __restrict__ targets,
    const float* __restrict__ cw, float* __restrict__ out)
{
    __shared__ __align__(16) float sP[NROWS * SMW4];
    __shared__ __align__(4)  unsigned char sTm[NROWS * SMW4];
    __shared__ float red[NWARP][4];
    __shared__ float s_dice[NPLANE];
    __shared__ float s_mm[NPLANE];
    __shared__ int s_isLast;

    const int plane = blockIdx.y;
    const int row0  = blockIdx.x * TILE_H;
    const float* lg = logits  + (size_t)plane * HH * WW;
    const float* tg = targets + (size_t)plane * HH * WW;
    const int tid = threadIdx.x;

    float s_pt = 0.f, s_p = 0.f, s_t = 0.f;
    int s_mi = 0;

    // ---- zero the left/right halo pads (cols 0..3 and 516..519) ----
    for (int i = tid; i < NROWS * 8; i += NT) {
        int r = i >> 3, c = i & 7;
        int idx = r * SMW4 + ((c < 4) ? c : 512 + c);
        sP[idx] = 0.f;
        sTm[idx] = 0;
    }

    // ---- staging: 18 rows x 128 float4 groups; dice sums fused here ----
    for (int i = tid; i < NROWS * 128; i += NT) {
        int r = i >> 7, g = i & 127;
        int gr = row0 - 1 + r;
        float4 pv = make_float4(0.f, 0.f, 0.f, 0.f);
        float4 tv = make_float4(0.f, 0.f, 0.f, 0.f);
        if ((unsigned)gr < HH) {
            float4 x = *((const float4*)(lg + (size_t)gr * WW) + g);
            tv = *((const float4*)(tg + (size_t)gr * WW) + g);
            pv.x = __fdividef(1.f, 1.f + __expf(-x.x));
            pv.y = __fdividef(1.f, 1.f + __expf(-x.y));
            pv.z = __fdividef(1.f, 1.f + __expf(-x.z));
            pv.w = __fdividef(1.f, 1.f + __expf(-x.w));
        }
        *(float4*)&sP[r * SMW4 + 4 + 4 * g] = pv;
        // t in {0.0f, 1.0f} exactly: bit 29 of the fp32 pattern is the value
        unsigned pk = (__float_as_uint(tv.x) >> 29)
                    | ((__float_as_uint(tv.y) >> 29) << 8)
                    | ((__float_as_uint(tv.z) >> 29) << 16)
                    | ((__float_as_uint(tv.w) >> 29) << 24);
        *(unsigned*)&sTm[r * SMW4 + 4 + 4 * g] = pk;
        if (r >= 1 && r <= TILE_H) {   // interior rows of this strip only
            s_pt += pv.x * tv.x + pv.y * tv.y + pv.z * tv.z + pv.w * tv.w;
            s_p  += (pv.x + pv.y) + (pv.z + pv.w);
            s_t  += (tv.x + tv.y) + (tv.z + tv.w);
        }
    }
    __syncthreads();

    // ---- rolling Sobel: thread owns 4 columns, walks 8 rows ----
    const int cg  = tid & 127;
    const int k0  = (tid >> 7) << 3;      // 0 or 8
    const int col = 4 + 4 * cg;
    const float* pbase = sP + col;
    const unsigned char* tbase = sTm + col;

    HR h0 = hrow(pbase + k0 * SMW4, tbase + k0 * SMW4);
    HR h1 = hrow(pbase + (k0 + 1) * SMW4, tbase + (k0 + 1) * SMW4);

    #pragma unroll
    for (int k = 0; k < 8; k++) {
        HR h2 = hrow(pbase + (k0 + k + 2) * SMW4, tbase + (k0 + k + 2) * SMW4);

        float gx0 = __fmaf_rn(2.f, h1.d0, h0.d0 + h2.d0);
        float gx1 = __fmaf_rn(2.f, h1.d1, h0.d1 + h2.d1);
        float gx2 = __fmaf_rn(2.f, h1.d2, h0.d2 + h2.d2);
        float gx3 = __fmaf_rn(2.f, h1.d3, h0.d3 + h2.d3);
        float gy0 = h2.s0 - h0.s0;
        float gy1 = h2.s1 - h0.s1;
        float gy2 = h2.s2 - h0.s2;
        float gy3 = h2.s3 - h0.s3;
        bool pb0 = __fmaf_rn(gx0, gx0, gy0 * gy0) > 0.25f;
        bool pb1 = __fmaf_rn(gx1, gx1, gy1 * gy1) > 0.25f;
        bool pb2 = __fmaf_rn(gx2, gx2, gy2 * gy2) > 0.25f;
        bool pb3 = __fmaf_rn(gx3, gx3, gy3 * gy3) > 0.25f;

        // packed-byte target Sobel: bias makes lanes carry-free
        unsigned hx = h0.db + 2u * h1.db + h2.db;        // lane==8  <=> hx_true==0
        unsigned hy = (h2.sb + 0x04040404u) - h0.sb;     // lane==4  <=> hy_true==0
        unsigned cmb = (hx ^ 0x08080808u) | (hy ^ 0x04040404u);

        s_mi += (int)(pb0 != ((cmb & 0x000000FFu) != 0));
        s_mi += (int)(pb1 != ((cmb & 0x0000FF00u) != 0));
        s_mi += (int)(pb2 != ((cmb & 0x00FF0000u) != 0));
        s_mi += (int)(pb3 != ((cmb >> 24) != 0));

        h0 = h1; h1 = h2;
    }

    // ---- block reduce ----
    float s_m = (float)s_mi;
    #pragma unroll
    for (int o = 16; o > 0; o >>= 1) {
        s_pt += __shfl_down_sync(0xffffffffu, s_pt, o);
        s_p  += __shfl_down_sync(0xffffffffu, s_p,  o);
        s_t  += __shfl_down_sync(0xffffffffu, s_t,  o);
        s_m  += __shfl_down_sync(0xffffffffu, s_m,  o);
    }
    int w = tid >> 5, lane = tid & 31;
    if (lane == 0) {
        red[w][0] = s_pt; red[w][1] = s_p; red[w][2] = s_t; red[w][3] = s_m;
    }
    __syncthreads();
    if (tid == 0) {
        float a = 0.f, b = 0.f, c2 = 0.f, d = 0.f;
        #pragma unroll
        for (int j = 0; j < NWARP; j++) {
            a += red[j][0]; b += red[j][1]; c2 += red[j][2]; d += red[j][3];
        }
        g_part[plane * NSTRIP + blockIdx.x] = make_float4(a, b, c2, d);
        __threadfence();
        int v = atomicAdd(&g_ctr, 1);
        s_isLast = (v == NBLK - 1);
    }
    __syncthreads();

    // ---- final reduction in the last block ----
    if (s_isLast) {
        __threadfence();
        if (tid < NPLANE) {
            float a = 0.f, b = 0.f, c2 = 0.f, m = 0.f;
            for (int s = 0; s < NSTRIP; s++) {
                float4 v = g_part[tid * NSTRIP + s];
                a += v.x; b += v.y; c2 += v.z; m += v.w;
            }
            s_dice[tid] = (2.0f * a + 1.0f) / (b + c2 + 1.0f);  // SMOOTH=1
            s_mm[tid] = m;
        }
        __syncthreads();
        if (tid == 0) {
            float mt = 0.0f;
            #pragma unroll
            for (int j = 0; j < NPLANE; j++) mt += s_mm[j];

            float wsum = 0.0f, dl = 0.0f;
            #pragma unroll
            for (int cc2 = 0; cc2 < CC; cc2++) {
                float acc = 0.0f;
                #pragma unroll
                for (int b = 0; b < BB; b++) acc += s_dice[b * CC + cc2];
                dl += cw[cc2] * (1.0f - acc / (float)BB);
                wsum += cw[cc2];
            }
            dl /= wsum;
            float bl = 100.0f * mt / (float)((long long)BB * CC * HH * WW);
            out[0] = 0.7f * dl + 0.3f * bl;
            g_ctr = 0;   // reset for next graph replay
        }
    }
}

extern "C" void kernel_launch(void* const* d_in, const int* in_sizes, int n_in,
                              void* d_out, int out_size)
{
    const float* logits  = (const float*)d_in[0];
    const float* targets = (const float*)d_in[1];
    const float* cw      = (const float*)d_in[2];

    dim3 grid(NSTRIP, NPLANE);
    loss_fused<<<grid, NT>>>(logits, targets, cw, (float*)d_out);
}

// round 4
// speedup vs baseline: 2.5393x; 1.0314x over previous
#include <cuda_runtime.h>

#define BB 8
#define CC 4
#define HH 512
#define WW 512
#define RPW 16                         // rows per warp strip
#define NSTRIPS (HH / RPW)             // 32
#define NPLANE (BB * CC)               // 32
#define CGRP 4                         // column groups of 128
#define NT 256
#define WPB (NT / 32)                  // 8 warps/block
#define NBLK (NPLANE * NSTRIPS * CGRP / WPB)   // 512

// One float4 partial per block (pt, p, t, mismatch). Block b covers a single
// plane (b>>4), so plane p's partials are blocks [16p, 16p+16).
__device__ float4 g_part[NBLK];
__device__ int g_ctr = 0;

__device__ __forceinline__ float sigm(float x) {
    float t;
    asm("tanh.approx.f32 %0, %1;" : "=f"(t) : "f"(0.5f * x));
    return __fmaf_rn(0.5f, t, 0.5f);
}
__device__ __forceinline__ unsigned prmt(unsigned a, unsigned b, unsigned s) {
    unsigned r;
    asm("prmt.b32 %0, %1, %2, %3;" : "=r"(r) : "r"(a), "r"(b), "r"(s));
    return r;
}

struct Row {
    float s0, s1, s2, s3, d0, d1, d2, d3;   // horizontal sobel partials (probs)
    unsigned sb, db;                        // packed-byte partials (targets)
};

// Fetch one image row (or zero halo), build horizontal partials, optionally
// accumulate dice sums. Horizontal neighbors via warp shuffle; warp-edge
// lanes (0 / 31) do predicated scalar loads.
template <bool DICE>
__device__ __forceinline__ Row fetch(const float* __restrict__ lg,
                                     const float* __restrict__ tg,
                                     int gr, int c0, int lane,
                                     bool lEdge, bool rEdge,
                                     float& s_pt, float& s_p, int& s_ti)
{
    float4 pv = make_float4(0.f, 0.f, 0.f, 0.f);
    unsigned tw = 0;
    const bool in = ((unsigned)gr < (unsigned)HH);
    const float* rowp = lg + (size_t)gr * WW + c0;
    const float* rowt = tg + (size_t)gr * WW + c0;
    if (in) {
        float4 x  = __ldg((const float4*)rowp);
        float4 tv = __ldg((const float4*)rowt);
        pv.x = sigm(x.x); pv.y = sigm(x.y); pv.z = sigm(x.z); pv.w = sigm(x.w);
        // pack targets (t in {0.0f,1.0f}): byte3 of bits is 0x3F/0x00, byte0 always 0
        unsigned p1 = prmt(__float_as_uint(tv.x), __float_as_uint(tv.y), 0x0073u);
        unsigned p2 = prmt(__float_as_uint(tv.z), __float_as_uint(tv.w), 0x7300u);
        tw = (p1 | p2) & 0x01010101u;
        if (DICE) {
            s_pt = __fmaf_rn(pv.x, tv.x, s_pt);
            s_pt = __fmaf_rn(pv.y, tv.y, s_pt);
            s_pt = __fmaf_rn(pv.z, tv.z, s_pt);
            s_pt = __fmaf_rn(pv.w, tv.w, s_pt);
            s_p += (pv.x + pv.y) + (pv.z + pv.w);
            s_ti += __popc(tw);               // bytes are 0/1
        }
    }
    // warp-edge neighbor values
    float eL = 0.f, eR = 0.f;
    unsigned tL = 0, tR = 0;
    if (lane == 0 && lEdge && in) {
        eL = sigm(__ldg(rowp - 1));
        tL = __float_as_uint(__ldg(rowt - 1)) >> 29;
    }
    if (lane == 31 && rEdge && in) {
        eR = sigm(__ldg(rowp + 4));
        tR = __float_as_uint(__ldg(rowt + 4)) >> 29;
    }
    float    plin = __shfl_up_sync(0xffffffffu, pv.w, 1);
    float    prin = __shfl_down_sync(0xffffffffu, pv.x, 1);
    unsigned twl  = __shfl_up_sync(0xffffffffu, tw, 1);
    unsigned twr  = __shfl_down_sync(0xffffffffu, tw, 1);
    float pl = (lane == 0)  ? eL : plin;
    float pr = (lane == 31) ? eR : prin;
    unsigned tl = (lane == 0)  ? tL : (twl >> 24);
    unsigned tr = (lane == 31) ? tR : (twr & 0xffu);

    Row h;
    h.s0 = __fmaf_rn(2.f, pv.x, pl   + pv.y); h.d0 = pv.y - pl;
    h.s1 = __fmaf_rn(2.f, pv.y, pv.x + pv.z); h.d1 = pv.z - pv.x;
    h.s2 = __fmaf_rn(2.f, pv.z, pv.y + pv.w); h.d2 = pv.w - pv.y;
    h.s3 = __fmaf_rn(2.f, pv.w, pv.z + pr);   h.d3 = pr   - pv.z;
    unsigned wl = (tw << 8) | tl;
    unsigned wr = (tw >> 8) | (tr << 24);
    h.sb = wl + 2u * tw + wr;                 // lanes in [0,4]
    h.db = (wr + 0x02020202u) - wl;           // lanes in [1,3] (bias +2)
    return h;
}

__device__ __forceinline__ int combine(const Row& h0, const Row& h1, const Row& h2)
{
    float gx0 = __fmaf_rn(2.f, h1.d0, h0.d0 + h2.d0);
    float gx1 = __fmaf_rn(2.f, h1.d1, h0.d1 + h2.d1);
    float gx2 = __fmaf_rn(2.f, h1.d2, h0.d2 + h2.d2);
    float gx3 = __fmaf_rn(2.f, h1.d3, h0.d3 + h2.d3);
    float gy0 = h2.s0 - h0.s0;
    float gy1 = h2.s1 - h0.s1;
    float gy2 = h2.s2 - h0.s2;
    float gy3 = h2.s3 - h0.s3;
    bool pb0 = __fmaf_rn(gx0, gx0, gy0 * gy0) > 0.25f;
    bool pb1 = __fmaf_rn(gx1, gx1, gy1 * gy1) > 0.25f;
    bool pb2 = __fmaf_rn(gx2, gx2, gy2 * gy2) > 0.25f;
    bool pb3 = __fmaf_rn(gx3, gx3, gy3 * gy3) > 0.25f;

    unsigned hx = h0.db + 2u * h1.db + h2.db;     // ==8 per lane <=> hx_true==0
    unsigned hy = (h2.sb + 0x04040404u) - h0.sb;  // ==4 per lane <=> hy_true==0
    unsigned cmb = (hx ^ 0x08080808u) | (hy ^ 0x04040404u);

    int m = 0;
    m += (int)(pb0 != ((cmb & 0x000000FFu) != 0));
    m += (int)(pb1 != ((cmb & 0x0000FF00u) != 0));
    m += (int)(pb2 != ((cmb & 0x00FF0000u) != 0));
    m += (int)(pb3 != ((cmb >> 24) != 0));
    return m;
}

__global__ __launch_bounds__(NT) void loss_fused(
    const float* __restrict__ logits, const float* __restrict__ targets,
    const float* __restrict__ cw, float* __restrict__ out)
{
    __shared__ float red[WPB][4];
    __shared__ float s_dice[NPLANE];
    __shared__ float s_mm[NPLANE];
    __shared__ int s_isLast;

    const int lane = threadIdx.x & 31;
    const int gw = blockIdx.x * WPB + (threadIdx.x >> 5);
    const int cg    = gw & 3;
    const int strip = (gw >> 2) & (NSTRIPS - 1);
    const int plane = gw >> 7;
    const int c0 = cg * 128 + lane * 4;
    const bool lEdge = (cg > 0);
    const bool rEdge = (cg < 3);
    const int row0 = strip * RPW;

    const float* lg = logits  + (size_t)plane * HH * WW;
    const float* tg = targets + (size_t)plane * HH * WW;

    float s_pt = 0.f, s_p = 0.f;
    int s_ti = 0, s_mi = 0;

    Row h0 = fetch<false>(lg, tg, row0 - 1, c0, lane, lEdge, rEdge, s_pt, s_p, s_ti);
    Row h1 = fetch<true >(lg, tg, row0,     c0, lane, lEdge, rEdge, s_pt, s_p, s_ti);
    #pragma unroll
    for (int k = 0; k < RPW - 1; k++) {
        Row h2 = fetch<true>(lg, tg, row0 + k + 1, c0, lane, lEdge, rEdge, s_pt, s_p, s_ti);
        s_mi += combine(h0, h1, h2);
        h0 = h1; h1 = h2;
    }
    {   // last window: bottom halo row (no dice)
        Row h2 = fetch<false>(lg, tg, row0 + RPW, c0, lane, lEdge, rEdge, s_pt, s_p, s_ti);
        s_mi += combine(h0, h1, h2);
    }

    // ---- warp reduce ----
    float s_t = (float)s_ti, s_m = (float)s_mi;
    #pragma unroll
    for (int o = 16; o > 0; o >>= 1) {
        s_pt += __shfl_down_sync(0xffffffffu, s_pt, o);
        s_p  += __shfl_down_sync(0xffffffffu, s_p,  o);
        s_t  += __shfl_down_sync(0xffffffffu, s_t,  o);
        s_m  += __shfl_down_sync(0xffffffffu, s_m,  o);
    }
    int w = threadIdx.x >> 5;
    if (lane == 0) {
        red[w][0] = s_pt; red[w][1] = s_p; red[w][2] = s_t; red[w][3] = s_m;
    }
    __syncthreads();
    if (threadIdx.x == 0) {
        float a = 0.f, b = 0.f, c2 = 0.f, d = 0.f;
        #pragma unroll
        for (int j = 0; j < WPB; j++) {
            a += red[j][0]; b += red[j][1]; c2 += red[j][2]; d += red[j][3];
        }
        g_part[blockIdx.x] = make_float4(a, b, c2, d);
        __threadfence();
        int v = atomicAdd(&g_ctr, 1);
        s_isLast = (v == NBLK - 1);
    }
    __syncthreads();

    // ---- final reduction in last block ----
    if (s_isLast) {
        __threadfence();
        int tid = threadIdx.x;
        if (tid < NPLANE) {
            float a = 0.f, b = 0.f, c2 = 0.f, m = 0.f;
            #pragma unroll 4
            for (int s = 0; s < NBLK / NPLANE; s++) {
                float4 v = g_part[tid * (NBLK / NPLANE) + s];
                a += v.x; b += v.y; c2 += v.z; m += v.w;
            }
            s_dice[tid] = (2.0f * a + 1.0f) / (b + c2 + 1.0f);  // SMOOTH=1
            s_mm[tid] = m;
        }
        __syncthreads();
        if (tid == 0) {
            float mt = 0.0f;
            #pragma unroll
            for (int j = 0; j < NPLANE; j++) mt += s_mm[j];

            float wsum = 0.0f, dl = 0.0f;
            #pragma unroll
            for (int c = 0; c < CC; c++) {
                float acc = 0.0f;
                #pragma unroll
                for (int b = 0; b < BB; b++) acc += s_dice[b * CC + c];
                dl += cw[c] * (1.0f - acc / (float)BB);
                wsum += cw[c];
            }
            dl /= wsum;
            float bl = 100.0f * mt / (float)((long long)BB * CC * HH * WW);
            out[0] = 0.7f * dl + 0.3f * bl;
            g_ctr = 0;   // reset for next graph replay
        }
    }
}

extern "C" void kernel_launch(void* const* d_in, const int* in_sizes, int n_in,
                              void* d_out, int out_size)
{
    const float* logits  = (const float*)d_in[0];
    const float* targets = (const float*)d_in[1];
    const float* cw      = (const float*)d_in[2];

    loss_fused<<<NBLK, NT>>>(logits, targets, cw, (float*)d_out);
}